// round 11
// baseline (speedup 1.0000x reference)
#include <cuda_runtime.h>
#include <cuda_fp16.h>
#include <cstdint>

// Fixed shapes for NKIMoELayer_24970939859026
#define T_TOK 4096
#define HDIM  2048
#define NEXP  16
#define TOPK  8             // reference uses experts 0..7 densely
#define IDIM  1408
#define TWOI  2816
#define KC    (TOPK * IDIM) // 11264

// Scratch (__device__ globals: allocation-free rule)
__device__ __half g_hid[(size_t)T_TOK * KC];          // hid' fp16       [t][e*IDIM+i]
__device__ float  g_rw [T_TOK * TOPK];
__device__ float  g_rwt[NEXP * HDIM];                 // router_w^T      [e][h]
__device__ __half g_xh [(size_t)T_TOK * HDIM];        // fp16(X)         [t][h]
__device__ __half g_guh[(size_t)TOPK * HDIM * TWOI];  // fp16(gate_up)   [e][h][feat]
__device__ __half g_dwh[(size_t)KC * HDIM];           // fp16(down flat) [k][h]

__device__ __forceinline__ void mma_f16(float* c, const uint32_t* a, uint32_t b0, uint32_t b1) {
    asm volatile(
        "mma.sync.aligned.m16n8k16.row.col.f32.f16.f16.f32 "
        "{%0,%1,%2,%3}, {%4,%5,%6,%7}, {%8,%9}, {%0,%1,%2,%3};"
        : "+f"(c[0]), "+f"(c[1]), "+f"(c[2]), "+f"(c[3])
        : "r"(a[0]), "r"(a[1]), "r"(a[2]), "r"(a[3]), "r"(b0), "r"(b1));
}

__device__ __forceinline__ void ldsm4(uint32_t* r, uint32_t addr) {
    asm volatile("ldmatrix.sync.aligned.m8n8.x4.shared.b16 {%0,%1,%2,%3}, [%4];"
        : "=r"(r[0]), "=r"(r[1]), "=r"(r[2]), "=r"(r[3]) : "r"(addr));
}
__device__ __forceinline__ void ldsm4t(uint32_t* r, uint32_t addr) {
    asm volatile("ldmatrix.sync.aligned.m8n8.x4.trans.shared.b16 {%0,%1,%2,%3}, [%4];"
        : "=r"(r[0]), "=r"(r[1]), "=r"(r[2]), "=r"(r[3]) : "r"(addr));
}

__device__ __forceinline__ void cp_async16(uint32_t smem, const void* gmem) {
    asm volatile("cp.async.cg.shared.global [%0], [%1], 16;" :: "r"(smem), "l"(gmem));
}
__device__ __forceinline__ void cp_commit() { asm volatile("cp.async.commit_group;"); }
template<int N> __device__ __forceinline__ void cp_wait() {
    asm volatile("cp.async.wait_group %0;" :: "n"(N));
}

// Swizzled store offsets; chunk = 16B; chunk position ^= (row & 7) (low 3 bits).
__device__ __forceinline__ uint32_t sw128(int row, int c) {
    return (uint32_t)(row * 128 + ((c ^ (row & 7)) << 4));
}
__device__ __forceinline__ uint32_t sw256(int row, int c) {
    return (uint32_t)(row * 256 + ((c ^ (row & 7)) << 4));
}
__device__ __forceinline__ uint32_t sw512(int row, int c) {
    return (uint32_t)(row * 512 + ((c ^ (row & 7)) << 4));
}
// A-fragment ldmatrix address ([m][k] tile, 128B rows):
// lr = lane&7, hm = (lane>>3)&1 (m half), hk = lane>>4 (k chunk +0/+1).
__device__ __forceinline__ uint32_t ldsmA_addr(uint32_t tile, int rowbase, int cb,
                                               int lr, int hm, int hk) {
    int row = rowbase + hm * 8 + lr;
    return tile + (uint32_t)(row * 128) + (uint32_t)((((cb + hk) ^ (row & 7)) << 4));
}
// B-fragment (trans) addresses for [k][n] tiles (256B / 512B rows):
// kr = lane&7, nc = (lane>>3)&1 (n 8-block), kh = lane>>4 (k 8-block).
__device__ __forceinline__ uint32_t ldsmBt256(uint32_t tile, int kbase, int ncb,
                                              int kr, int nc, int kh) {
    int row = kbase + kh * 8 + kr;
    return tile + (uint32_t)(row * 256) + (uint32_t)((((ncb + nc) ^ kr) << 4));
}
__device__ __forceinline__ uint32_t ldsmBt512(uint32_t tile, int kbase, int ncb,
                                              int kr, int nc, int kh) {
    int row = kbase + kh * 8 + kr;
    return tile + (uint32_t)(row * 512) + (uint32_t)((((ncb + nc) ^ kr) << 4));
}

// ---------------------------------------------------------------------------
// Pre-pass: fp32 -> fp16 straight copies
// ---------------------------------------------------------------------------
__global__ __launch_bounds__(256) void cvt_gu_kernel(const float* __restrict__ src) {
    const long long n4 = (long long)TOPK * HDIM * TWOI / 4;
    long long i = (long long)blockIdx.x * blockDim.x + threadIdx.x;
    long long st = (long long)gridDim.x * blockDim.x;
    for (; i < n4; i += st) {
        float4 v = ((const float4*)src)[i];
        ((__half2*)g_guh)[i * 2 + 0] = __floats2half2_rn(v.x, v.y);
        ((__half2*)g_guh)[i * 2 + 1] = __floats2half2_rn(v.z, v.w);
    }
}
__global__ __launch_bounds__(256) void cvt_dw_kernel(const float* __restrict__ src) {
    const long long n4 = (long long)KC * HDIM / 4;
    long long i = (long long)blockIdx.x * blockDim.x + threadIdx.x;
    long long st = (long long)gridDim.x * blockDim.x;
    for (; i < n4; i += st) {
        float4 v = ((const float4*)src)[i];
        ((__half2*)g_dwh)[i * 2 + 0] = __floats2half2_rn(v.x, v.y);
        ((__half2*)g_dwh)[i * 2 + 1] = __floats2half2_rn(v.z, v.w);
    }
}
// router_w[h][e] -> g_rwt[e][h]
__global__ __launch_bounds__(256) void tpose_rw_kernel(const float* __restrict__ src) {
    int i = blockIdx.x * blockDim.x + threadIdx.x;
    if (i < NEXP * HDIM) {
        int e = i / HDIM, h = i % HDIM;
        g_rwt[i] = src[h * NEXP + e];
    }
}

// ---------------------------------------------------------------------------
// Router: one warp per token; ALSO converts X -> g_xh (fused cvt_x).
// ---------------------------------------------------------------------------
__global__ __launch_bounds__(256) void router_kernel(
    const float* __restrict__ x, float* __restrict__ w_tail)
{
    int t = (blockIdx.x * blockDim.x + threadIdx.x) >> 5;
    int lane = threadIdx.x & 31;
    if (t >= T_TOK) return;
    const float* xr = x + (size_t)t * HDIM;
    __half* xo = g_xh + (size_t)t * HDIM;

    float acc[NEXP] = {};
    for (int h0 = lane * 4; h0 < HDIM; h0 += 128) {
        float4 xv = *(const float4*)(xr + h0);
        *(__half2*)(xo + h0)     = __floats2half2_rn(xv.x, xv.y);
        *(__half2*)(xo + h0 + 2) = __floats2half2_rn(xv.z, xv.w);
        #pragma unroll
        for (int e = 0; e < NEXP; e++) {
            float4 wv = *(const float4*)(g_rwt + e * HDIM + h0);
            acc[e] += xv.x * wv.x + xv.y * wv.y + xv.z * wv.z + xv.w * wv.w;
        }
    }
    #pragma unroll
    for (int e = 0; e < NEXP; e++) {
        #pragma unroll
        for (int o = 16; o; o >>= 1) acc[e] += __shfl_xor_sync(0xFFFFFFFFu, acc[e], o);
    }
    if (lane == 0) {
        float m = acc[0];
        #pragma unroll
        for (int e = 1; e < NEXP; e++) m = fmaxf(m, acc[e]);
        float p[NEXP];
        #pragma unroll
        for (int e = 0; e < NEXP; e++) p[e] = expf(acc[e] - m);
        float v[TOPK]; float ssel = 0.f;
        #pragma unroll
        for (int k = 0; k < TOPK; k++) {
            int bi = 0; float bv = -1.f;
            #pragma unroll
            for (int e = 0; e < NEXP; e++) if (p[e] > bv) { bv = p[e]; bi = e; }
            p[bi] = -2.f; v[k] = bv; ssel += bv;
        }
        float inv = 1.f / ssel;
        #pragma unroll
        for (int k = 0; k < TOPK; k++) {
            float wv = v[k] * inv;
            g_rw[t * TOPK + k] = wv;
            if (w_tail) w_tail[t * TOPK + k] = wv;
        }
    }
}

#define NSTAGE  3
#define STAGE_B 49152    // A 16 KB + B region 32 KB
#define G_SMEM  (NSTAGE * STAGE_B)

// ---------------------------------------------------------------------------
// GEMM1: hid'[t, e*IDIM+n] = w[t,e] * silu(X@GUe[:,n]) * (X@GUe[:,IDIM+n])
// 512 thr, BM=128, BN=128(gate)+128(up), BK=64. Warps 4m x 4n, warp 32x(32+32).
// ---------------------------------------------------------------------------
__global__ __launch_bounds__(512, 1) void gemm1_kernel()
{
    extern __shared__ __align__(128) char smem[];
    const uint32_t sbase = (uint32_t)__cvta_generic_to_shared(smem);
    const int m0 = blockIdx.x * 128;
    const int n0 = blockIdx.y * 128;
    const int e  = blockIdx.z;
    const __half* Bbase = g_guh + (size_t)e * HDIM * TWOI;   // [h][feat]

    const int tid = threadIdx.x;
    const int wid = tid >> 5, lane = tid & 31;
    const int wm = wid & 3, wn = wid >> 2;   // 4 x 4
    const int g = lane >> 2, tg = lane & 3;
    const int lr = lane & 7, hm = (lane >> 3) & 1, hk = lane >> 4;

    float accG[2][4][4] = {};
    float accU[2][4][4] = {};
    const int KITER = HDIM / 64;   // 32

    auto load_stage = [&](int s, int kk) {
        uint32_t st = sbase + (uint32_t)(s * STAGE_B);
        // A: 128 rows x 8 chunks = 1024 jobs -> 2/thread
        #pragma unroll
        for (int i = 0; i < 2; i++) {
            int idx = tid + i * 512;
            int row = idx >> 3, c = idx & 7;
            cp_async16(st + sw128(row, c), g_xh + (size_t)(m0 + row) * HDIM + kk + c * 8);
        }
        // G,U tiles [k=64][n=128] (256B rows, 16 chunks): 2048 jobs -> 4/thread
        #pragma unroll
        for (int i = 0; i < 4; i++) {
            int idx = tid + i * 512;
            int up = idx >> 10;                // 0: gate, 1: up
            int rem = idx & 1023;
            int r = rem >> 4, c = rem & 15;
            int feat = up ? (IDIM + n0 + c * 8) : (n0 + c * 8);
            uint32_t dst = st + 16384 + (uint32_t)(up * 16384);
            cp_async16(dst + sw256(r, c), Bbase + (size_t)(kk + r) * TWOI + feat);
        }
    };

    #pragma unroll
    for (int s = 0; s < NSTAGE - 1; s++) { load_stage(s, s * 64); cp_commit(); }

    for (int it = 0; it < KITER; it++) {
        cp_wait<NSTAGE - 2>();
        __syncthreads();

        int nxt = it + NSTAGE - 1;
        if (nxt < KITER) load_stage(nxt % NSTAGE, nxt * 64);
        cp_commit();

        const uint32_t At = sbase + (uint32_t)((it % NSTAGE) * STAGE_B);
        const uint32_t Gt = At + 16384;
        const uint32_t Ut = At + 32768;

        #pragma unroll
        for (int ks = 0; ks < 4; ks++) {
            int cb = ks * 2;                      // A k-chunk base
            int kb = ks * 16;                     // B k-row base
            uint32_t a[2][4];
            #pragma unroll
            for (int mi = 0; mi < 2; mi++)
                ldsm4(a[mi], ldsmA_addr(At, wm * 32 + mi * 16, cb, lr, hm, hk));
            uint32_t bg[2][4], bu[2][4];
            #pragma unroll
            for (int p = 0; p < 2; p++) {
                int ncb = wn * 4 + p * 2;
                ldsm4t(bg[p], ldsmBt256(Gt, kb, ncb, lr, hm, hk));
                ldsm4t(bu[p], ldsmBt256(Ut, kb, ncb, lr, hm, hk));
            }
            #pragma unroll
            for (int ni = 0; ni < 4; ni++) {
                int p = ni >> 1, o = ni & 1;
                #pragma unroll
                for (int mi = 0; mi < 2; mi++) {
                    mma_f16(accG[mi][ni], a[mi], bg[p][o], bg[p][o + 2]);
                    mma_f16(accU[mi][ni], a[mi], bu[p][o], bu[p][o + 2]);
                }
            }
        }
    }

    // Epilogue: hid' = w * silu(gate) * up -> fp16
    #pragma unroll
    for (int mi = 0; mi < 2; mi++) {
        #pragma unroll
        for (int r2 = 0; r2 < 2; r2++) {
            int t = m0 + wm * 32 + mi * 16 + g + r2 * 8;
            float w = g_rw[t * TOPK + e];
            __half* dst = g_hid + (size_t)t * KC + (size_t)e * IDIM + n0;
            #pragma unroll
            for (int ni = 0; ni < 4; ni++) {
                int col = wn * 32 + ni * 8 + tg * 2;
                float gv0 = accG[mi][ni][r2 * 2 + 0], uv0 = accU[mi][ni][r2 * 2 + 0];
                float gv1 = accG[mi][ni][r2 * 2 + 1], uv1 = accU[mi][ni][r2 * 2 + 1];
                float h0 = (gv0 / (1.f + expf(-gv0))) * uv0 * w;
                float h1 = (gv1 / (1.f + expf(-gv1))) * uv1 * w;
                *(__half2*)(dst + col) = __floats2half2_rn(h0, h1);
            }
        }
    }
}

// ---------------------------------------------------------------------------
// GEMM2: out[4096,2048] = g_hid[4096,11264] @ down_flat[11264,2048]
// 512 thr, BM=128, BN=256, BK=64. Warps 4m x 4n, warp tile 32x64.
// B tile [k=64][n=256] (512B rows), fragments via ldmatrix.trans.
// ---------------------------------------------------------------------------
__global__ __launch_bounds__(512, 1) void gemm2_kernel(float* __restrict__ OUT)
{
    extern __shared__ __align__(128) char smem[];
    const uint32_t sbase = (uint32_t)__cvta_generic_to_shared(smem);
    const int m0 = blockIdx.x * 128;
    const int n0 = blockIdx.y * 256;

    const int tid = threadIdx.x;
    const int wid = tid >> 5, lane = tid & 31;
    const int wm = wid & 3, wn = wid >> 2;   // 4 x 4
    const int g = lane >> 2, tg = lane & 3;
    const int lr = lane & 7, hm = (lane >> 3) & 1, hk = lane >> 4;

    float acc[2][8][4] = {};
    const int KITER = KC / 64;   // 176

    auto load_stage = [&](int s, int kk) {
        uint32_t st = sbase + (uint32_t)(s * STAGE_B);
        // A: 128 rows x 8 chunks = 1024 jobs -> 2/thread
        #pragma unroll
        for (int i = 0; i < 2; i++) {
            int idx = tid + i * 512;
            int row = idx >> 3, c = idx & 7;
            cp_async16(st + sw128(row, c), g_hid + (size_t)(m0 + row) * KC + kk + c * 8);
        }
        // B tile [k=64][n=256]: 64 rows x 32 chunks = 2048 jobs -> 4/thread
        #pragma unroll
        for (int i = 0; i < 4; i++) {
            int idx = tid + i * 512;
            int r = idx >> 5, c = idx & 31;
            cp_async16(st + 16384 + sw512(r, c),
                       g_dwh + (size_t)(kk + r) * HDIM + n0 + c * 8);
        }
    };

    #pragma unroll
    for (int s = 0; s < NSTAGE - 1; s++) { load_stage(s, s * 64); cp_commit(); }

    for (int it = 0; it < KITER; it++) {
        cp_wait<NSTAGE - 2>();
        __syncthreads();

        int nxt = it + NSTAGE - 1;
        if (nxt < KITER) load_stage(nxt % NSTAGE, nxt * 64);
        cp_commit();

        const uint32_t At = sbase + (uint32_t)((it % NSTAGE) * STAGE_B);
        const uint32_t Bt = At + 16384;

        #pragma unroll
        for (int ks = 0; ks < 4; ks++) {
            int cb = ks * 2;
            int kb = ks * 16;
            uint32_t a[2][4];
            #pragma unroll
            for (int mi = 0; mi < 2; mi++)
                ldsm4(a[mi], ldsmA_addr(At, wm * 32 + mi * 16, cb, lr, hm, hk));
            uint32_t b[4][4];
            #pragma unroll
            for (int p = 0; p < 4; p++) {
                int ncb = wn * 8 + p * 2;
                ldsm4t(b[p], ldsmBt512(Bt, kb, ncb, lr, hm, hk));
            }
            #pragma unroll
            for (int ni = 0; ni < 8; ni++) {
                int p = ni >> 1, o = ni & 1;
                #pragma unroll
                for (int mi = 0; mi < 2; mi++)
                    mma_f16(acc[mi][ni], a[mi], b[p][o], b[p][o + 2]);
            }
        }
    }

    #pragma unroll
    for (int mi = 0; mi < 2; mi++) {
        #pragma unroll
        for (int r2 = 0; r2 < 2; r2++) {
            int t = m0 + wm * 32 + mi * 16 + g + r2 * 8;
            #pragma unroll
            for (int ni = 0; ni < 8; ni++) {
                int col = n0 + wn * 64 + ni * 8 + tg * 2;
                float2 v;
                v.x = acc[mi][ni][r2 * 2 + 0];
                v.y = acc[mi][ni][r2 * 2 + 1];
                *(float2*)(OUT + (size_t)t * HDIM + col) = v;
            }
        }
    }
}

// ---------------------------------------------------------------------------
extern "C" void kernel_launch(void* const* d_in, const int* in_sizes, int n_in,
                              void* d_out, int out_size) {
    const float* x  = (const float*)d_in[0];
    const float* rw = (const float*)d_in[1];
    const float* gu = (const float*)d_in[2];
    const float* dw = (const float*)d_in[3];
    float* out = (float*)d_out;

    const long long OUT_ELEMS = (long long)T_TOK * HDIM;
    float* tail = nullptr;
    if ((long long)out_size >= OUT_ELEMS + (long long)T_TOK * TOPK)
        tail = out + OUT_ELEMS;

    cudaFuncSetAttribute(gemm1_kernel, cudaFuncAttributeMaxDynamicSharedMemorySize, G_SMEM);
    cudaFuncSetAttribute(gemm2_kernel, cudaFuncAttributeMaxDynamicSharedMemorySize, G_SMEM);

    tpose_rw_kernel<<<(NEXP * HDIM + 255) / 256, 256>>>(rw);
    cvt_gu_kernel<<<8192, 256>>>(gu);
    cvt_dw_kernel<<<8192, 256>>>(dw);
    router_kernel<<<T_TOK / 8, 256>>>(x, tail);

    dim3 grid1(T_TOK / 128, IDIM / 128, TOPK);   // (32, 11, 8)
    gemm1_kernel<<<grid1, 512, G_SMEM>>>();

    dim3 grid2(T_TOK / 128, HDIM / 256);         // (32, 8)
    gemm2_kernel<<<grid2, 512, G_SMEM>>>(out);
}

// round 12
// speedup vs baseline: 1.0277x; 1.0277x over previous
#include <cuda_runtime.h>
#include <cuda_fp16.h>
#include <cstdint>

// Fixed shapes for NKIMoELayer_24970939859026
#define T_TOK 4096
#define HDIM  2048
#define NEXP  16
#define TOPK  8             // reference uses experts 0..7 densely
#define IDIM  1408
#define TWOI  2816
#define KC    (TOPK * IDIM) // 11264

// Scratch (__device__ globals: allocation-free rule)
__device__ __half g_hid[(size_t)T_TOK * KC];          // hid' fp16       [t][e*IDIM+i]
__device__ float  g_rw [T_TOK * TOPK];
__device__ float  g_rwt[NEXP * HDIM];                 // router_w^T      [e][h]
__device__ __half g_xh [(size_t)T_TOK * HDIM];        // fp16(X)         [t][h]
__device__ __half g_guh[(size_t)TOPK * HDIM * TWOI];  // fp16(gate_up)   [e][h][feat]
__device__ __half g_dwh[(size_t)KC * HDIM];           // fp16(down flat) [k][h]

__device__ __forceinline__ void mma_f16(float* c, const uint32_t* a, uint32_t b0, uint32_t b1) {
    asm volatile(
        "mma.sync.aligned.m16n8k16.row.col.f32.f16.f16.f32 "
        "{%0,%1,%2,%3}, {%4,%5,%6,%7}, {%8,%9}, {%0,%1,%2,%3};"
        : "+f"(c[0]), "+f"(c[1]), "+f"(c[2]), "+f"(c[3])
        : "r"(a[0]), "r"(a[1]), "r"(a[2]), "r"(a[3]), "r"(b0), "r"(b1));
}

__device__ __forceinline__ void ldsm4(uint32_t* r, uint32_t addr) {
    asm volatile("ldmatrix.sync.aligned.m8n8.x4.shared.b16 {%0,%1,%2,%3}, [%4];"
        : "=r"(r[0]), "=r"(r[1]), "=r"(r[2]), "=r"(r[3]) : "r"(addr));
}
__device__ __forceinline__ void ldsm4t(uint32_t* r, uint32_t addr) {
    asm volatile("ldmatrix.sync.aligned.m8n8.x4.trans.shared.b16 {%0,%1,%2,%3}, [%4];"
        : "=r"(r[0]), "=r"(r[1]), "=r"(r[2]), "=r"(r[3]) : "r"(addr));
}

__device__ __forceinline__ void cp_async16(uint32_t smem, const void* gmem) {
    asm volatile("cp.async.cg.shared.global [%0], [%1], 16;" :: "r"(smem), "l"(gmem));
}
__device__ __forceinline__ void cp_commit() { asm volatile("cp.async.commit_group;"); }
template<int N> __device__ __forceinline__ void cp_wait() {
    asm volatile("cp.async.wait_group %0;" :: "n"(N));
}

// Swizzled store offsets; chunk = 16B; chunk position ^= (row & 7) (low 3 bits).
__device__ __forceinline__ uint32_t sw128(int row, int c) {
    return (uint32_t)(row * 128 + ((c ^ (row & 7)) << 4));
}
__device__ __forceinline__ uint32_t sw256(int row, int c) {
    return (uint32_t)(row * 256 + ((c ^ (row & 7)) << 4));
}
// A-fragment ldmatrix address ([m][k] tile, 128B rows):
// lr = lane&7, hm = (lane>>3)&1 (m half), hk = lane>>4 (k chunk +0/+1).
__device__ __forceinline__ uint32_t ldsmA_addr(uint32_t tile, int rowbase, int cb,
                                               int lr, int hm, int hk) {
    int row = rowbase + hm * 8 + lr;
    return tile + (uint32_t)(row * 128) + (uint32_t)((((cb + hk) ^ (row & 7)) << 4));
}
// B-fragment (trans) addresses for [k][n] tiles (128B / 256B rows):
// kr = lane&7, nc = (lane>>3)&1 (n 8-block), kh = lane>>4 (k 8-block).
__device__ __forceinline__ uint32_t ldsmBt128(uint32_t tile, int kbase, int ncb,
                                              int kr, int nc, int kh) {
    int row = kbase + kh * 8 + kr;
    return tile + (uint32_t)(row * 128) + (uint32_t)((((ncb + nc) ^ kr) << 4));
}
__device__ __forceinline__ uint32_t ldsmBt256(uint32_t tile, int kbase, int ncb,
                                              int kr, int nc, int kh) {
    int row = kbase + kh * 8 + kr;
    return tile + (uint32_t)(row * 256) + (uint32_t)((((ncb + nc) ^ kr) << 4));
}

// ---------------------------------------------------------------------------
// Pre-pass: fp32 -> fp16 straight copies
// ---------------------------------------------------------------------------
__global__ __launch_bounds__(256) void cvt_x_kernel(const float* __restrict__ src) {
    const long long n4 = (long long)T_TOK * HDIM / 4;
    long long i = (long long)blockIdx.x * blockDim.x + threadIdx.x;
    long long st = (long long)gridDim.x * blockDim.x;
    for (; i < n4; i += st) {
        float4 v = ((const float4*)src)[i];
        ((__half2*)g_xh)[i * 2 + 0] = __floats2half2_rn(v.x, v.y);
        ((__half2*)g_xh)[i * 2 + 1] = __floats2half2_rn(v.z, v.w);
    }
}
__global__ __launch_bounds__(256) void cvt_gu_kernel(const float* __restrict__ src) {
    const long long n4 = (long long)TOPK * HDIM * TWOI / 4;
    long long i = (long long)blockIdx.x * blockDim.x + threadIdx.x;
    long long st = (long long)gridDim.x * blockDim.x;
    for (; i < n4; i += st) {
        float4 v = ((const float4*)src)[i];
        ((__half2*)g_guh)[i * 2 + 0] = __floats2half2_rn(v.x, v.y);
        ((__half2*)g_guh)[i * 2 + 1] = __floats2half2_rn(v.z, v.w);
    }
}
__global__ __launch_bounds__(256) void cvt_dw_kernel(const float* __restrict__ src) {
    const long long n4 = (long long)KC * HDIM / 4;
    long long i = (long long)blockIdx.x * blockDim.x + threadIdx.x;
    long long st = (long long)gridDim.x * blockDim.x;
    for (; i < n4; i += st) {
        float4 v = ((const float4*)src)[i];
        ((__half2*)g_dwh)[i * 2 + 0] = __floats2half2_rn(v.x, v.y);
        ((__half2*)g_dwh)[i * 2 + 1] = __floats2half2_rn(v.z, v.w);
    }
}
// router_w[h][e] -> g_rwt[e][h]
__global__ __launch_bounds__(256) void tpose_rw_kernel(const float* __restrict__ src) {
    int i = blockIdx.x * blockDim.x + threadIdx.x;
    if (i < NEXP * HDIM) {
        int e = i / HDIM, h = i % HDIM;
        g_rwt[i] = src[h * NEXP + e];
    }
}

// ---------------------------------------------------------------------------
// Router: one warp per token; rwt gives fully coalesced weight reads.
// ---------------------------------------------------------------------------
__global__ __launch_bounds__(256) void router_kernel(
    const float* __restrict__ x, float* __restrict__ w_tail)
{
    int t = (blockIdx.x * blockDim.x + threadIdx.x) >> 5;
    int lane = threadIdx.x & 31;
    if (t >= T_TOK) return;
    const float* xr = x + (size_t)t * HDIM;

    float acc[NEXP] = {};
    for (int h0 = lane * 4; h0 < HDIM; h0 += 128) {
        float4 xv = *(const float4*)(xr + h0);
        #pragma unroll
        for (int e = 0; e < NEXP; e++) {
            float4 wv = *(const float4*)(g_rwt + e * HDIM + h0);
            acc[e] += xv.x * wv.x + xv.y * wv.y + xv.z * wv.z + xv.w * wv.w;
        }
    }
    #pragma unroll
    for (int e = 0; e < NEXP; e++) {
        #pragma unroll
        for (int o = 16; o; o >>= 1) acc[e] += __shfl_xor_sync(0xFFFFFFFFu, acc[e], o);
    }
    if (lane == 0) {
        float m = acc[0];
        #pragma unroll
        for (int e = 1; e < NEXP; e++) m = fmaxf(m, acc[e]);
        float p[NEXP];
        #pragma unroll
        for (int e = 0; e < NEXP; e++) p[e] = expf(acc[e] - m);
        float v[TOPK]; float ssel = 0.f;
        #pragma unroll
        for (int k = 0; k < TOPK; k++) {
            int bi = 0; float bv = -1.f;
            #pragma unroll
            for (int e = 0; e < NEXP; e++) if (p[e] > bv) { bv = p[e]; bi = e; }
            p[bi] = -2.f; v[k] = bv; ssel += bv;
        }
        float inv = 1.f / ssel;
        #pragma unroll
        for (int k = 0; k < TOPK; k++) {
            float wv = v[k] * inv;
            g_rw[t * TOPK + k] = wv;
            if (w_tail) w_tail[t * TOPK + k] = wv;
        }
    }
}

#define NSTAGE  3
#define STAGE_B 32768    // A 16 KB (128 rows x 128B) + B region 16 KB
#define G_SMEM  (NSTAGE * STAGE_B)

// ---------------------------------------------------------------------------
// GEMM1: hid'[t, e*IDIM+n] = w[t,e] * silu(X@GUe[:,n]) * (X@GUe[:,IDIM+n])
// BM=128, BN=64(gate)+64(up), BK=64. B tiles stored [k][n] (64 x 128B),
// fragments via ldmatrix.trans. 8 warps (4x2), warp 32x32(+32x32).
// Fragment double-buffering across ks.
// ---------------------------------------------------------------------------
__global__ __launch_bounds__(256, 2) void gemm1_kernel()
{
    extern __shared__ __align__(128) char smem[];
    const uint32_t sbase = (uint32_t)__cvta_generic_to_shared(smem);
    const int m0 = blockIdx.x * 128;
    const int n0 = blockIdx.y * 64;
    const int e  = blockIdx.z;
    const __half* Bbase = g_guh + (size_t)e * HDIM * TWOI;   // [h][feat]

    const int tid = threadIdx.x;
    const int wid = tid >> 5, lane = tid & 31;
    const int wm = wid & 3, wn = wid >> 2;
    const int g = lane >> 2, tg = lane & 3;
    const int lr = lane & 7, hm = (lane >> 3) & 1, hk = lane >> 4;

    float accG[2][4][4] = {};
    float accU[2][4][4] = {};
    const int KITER = HDIM / 64;   // 32

    auto load_stage = [&](int s, int kk) {
        uint32_t st = sbase + (uint32_t)(s * STAGE_B);
        #pragma unroll
        for (int i = 0; i < 4; i++) {
            int idx = tid + i * 256;
            int row = idx >> 3, c = idx & 7;
            cp_async16(st + sw128(row, c), g_xh + (size_t)(m0 + row) * HDIM + kk + c * 8);
        }
        #pragma unroll
        for (int i = 0; i < 4; i++) {
            int idx = tid + i * 256;
            int up = idx >> 9;                 // 0: gate, 1: up
            int r = (idx & 511) >> 3, c = idx & 7;     // r = k row, c = n chunk
            int feat = up ? (IDIM + n0 + c * 8) : (n0 + c * 8);
            uint32_t dst = st + 16384 + (uint32_t)(up * 8192);
            cp_async16(dst + sw128(r, c), Bbase + (size_t)(kk + r) * TWOI + feat);
        }
    };

    #pragma unroll
    for (int s = 0; s < NSTAGE - 1; s++) { load_stage(s, s * 64); cp_commit(); }

    auto frag_load = [&](uint32_t At, uint32_t Gt, uint32_t Ut, int ks,
                         uint32_t a[2][4], uint32_t bg[2][4], uint32_t bu[2][4]) {
        int cb = ks * 2, kb = ks * 16;
        #pragma unroll
        for (int mi = 0; mi < 2; mi++)
            ldsm4(a[mi], ldsmA_addr(At, wm * 32 + mi * 16, cb, lr, hm, hk));
        #pragma unroll
        for (int p = 0; p < 2; p++) {
            int ncb = wn * 4 + p * 2;
            ldsm4t(bg[p], ldsmBt128(Gt, kb, ncb, lr, hm, hk));
            ldsm4t(bu[p], ldsmBt128(Ut, kb, ncb, lr, hm, hk));
        }
    };
    auto frag_mma = [&](uint32_t a[2][4], uint32_t bg[2][4], uint32_t bu[2][4]) {
        #pragma unroll
        for (int ni = 0; ni < 4; ni++) {
            int p = ni >> 1, o = ni & 1;
            #pragma unroll
            for (int mi = 0; mi < 2; mi++) {
                mma_f16(accG[mi][ni], a[mi], bg[p][o], bg[p][o + 2]);
                mma_f16(accU[mi][ni], a[mi], bu[p][o], bu[p][o + 2]);
            }
        }
    };

    for (int it = 0; it < KITER; it++) {
        cp_wait<NSTAGE - 2>();
        __syncthreads();

        int nxt = it + NSTAGE - 1;
        if (nxt < KITER) load_stage(nxt % NSTAGE, nxt * 64);
        cp_commit();

        const uint32_t At = sbase + (uint32_t)((it % NSTAGE) * STAGE_B);
        const uint32_t Gt = At + 16384;
        const uint32_t Ut = At + 24576;

        uint32_t a0[2][4], bg0[2][4], bu0[2][4];
        uint32_t a1[2][4], bg1[2][4], bu1[2][4];
        frag_load(At, Gt, Ut, 0, a0, bg0, bu0);
        #pragma unroll
        for (int ks = 0; ks < 4; ks++) {
            if (ks & 1) {
                if (ks < 3) frag_load(At, Gt, Ut, ks + 1, a0, bg0, bu0);
                frag_mma(a1, bg1, bu1);
            } else {
                frag_load(At, Gt, Ut, ks + 1 > 3 ? 3 : ks + 1, a1, bg1, bu1);
                frag_mma(a0, bg0, bu0);
            }
        }
    }

    // Epilogue: hid' = w * silu(gate) * up -> fp16
    #pragma unroll
    for (int mi = 0; mi < 2; mi++) {
        #pragma unroll
        for (int r2 = 0; r2 < 2; r2++) {
            int t = m0 + wm * 32 + mi * 16 + g + r2 * 8;
            float w = g_rw[t * TOPK + e];
            __half* dst = g_hid + (size_t)t * KC + (size_t)e * IDIM + n0;
            #pragma unroll
            for (int ni = 0; ni < 4; ni++) {
                int col = wn * 32 + ni * 8 + tg * 2;
                float gv0 = accG[mi][ni][r2 * 2 + 0], uv0 = accU[mi][ni][r2 * 2 + 0];
                float gv1 = accG[mi][ni][r2 * 2 + 1], uv1 = accU[mi][ni][r2 * 2 + 1];
                float h0 = (gv0 / (1.f + expf(-gv0))) * uv0 * w;
                float h1 = (gv1 / (1.f + expf(-gv1))) * uv1 * w;
                *(__half2*)(dst + col) = __floats2half2_rn(h0, h1);
            }
        }
    }
}

// ---------------------------------------------------------------------------
// GEMM2: out[4096,2048] = g_hid[4096,11264] @ down_flat[11264,2048]
// BM=128, BN=128, BK=64. B tile stored [k=64][n=128] (256B rows),
// fragments via ldmatrix.trans. 8 warps (4x2), warp 32x64.
// Grid: n fastest (B L2-resident). Fragment double-buffering across ks.
// ---------------------------------------------------------------------------
__global__ __launch_bounds__(256, 2) void gemm2_kernel(float* __restrict__ OUT)
{
    extern __shared__ __align__(128) char smem[];
    const uint32_t sbase = (uint32_t)__cvta_generic_to_shared(smem);
    const int m0 = blockIdx.y * 128;
    const int n0 = blockIdx.x * 128;   // n fastest

    const int tid = threadIdx.x;
    const int wid = tid >> 5, lane = tid & 31;
    const int wm = wid & 3, wn = wid >> 2;
    const int g = lane >> 2, tg = lane & 3;
    const int lr = lane & 7, hm = (lane >> 3) & 1, hk = lane >> 4;

    float acc[2][8][4] = {};
    const int KITER = KC / 64;   // 176

    auto load_stage = [&](int s, int kk) {
        uint32_t st = sbase + (uint32_t)(s * STAGE_B);
        #pragma unroll
        for (int i = 0; i < 4; i++) {
            int idx = tid + i * 256;
            int row = idx >> 3, c = idx & 7;
            cp_async16(st + sw128(row, c), g_hid + (size_t)(m0 + row) * KC + kk + c * 8);
        }
        #pragma unroll
        for (int i = 0; i < 4; i++) {
            int idx = tid + i * 256;
            int r = idx >> 4, c = idx & 15;
            cp_async16(st + 16384 + sw256(r, c),
                       g_dwh + (size_t)(kk + r) * HDIM + n0 + c * 8);
        }
    };

    #pragma unroll
    for (int s = 0; s < NSTAGE - 1; s++) { load_stage(s, s * 64); cp_commit(); }

    auto frag_load = [&](uint32_t At, uint32_t Bt, int ks,
                         uint32_t a[2][4], uint32_t b[4][4]) {
        int cb = ks * 2, kb = ks * 16;
        #pragma unroll
        for (int mi = 0; mi < 2; mi++)
            ldsm4(a[mi], ldsmA_addr(At, wm * 32 + mi * 16, cb, lr, hm, hk));
        #pragma unroll
        for (int p = 0; p < 4; p++) {
            int ncb = wn * 8 + p * 2;
            ldsm4t(b[p], ldsmBt256(Bt, kb, ncb, lr, hm, hk));
        }
    };
    auto frag_mma = [&](uint32_t a[2][4], uint32_t b[4][4]) {
        #pragma unroll
        for (int ni = 0; ni < 8; ni++) {
            int p = ni >> 1, o = ni & 1;
            #pragma unroll
            for (int mi = 0; mi < 2; mi++)
                mma_f16(acc[mi][ni], a[mi], b[p][o], b[p][o + 2]);
        }
    };

    for (int it = 0; it < KITER; it++) {
        cp_wait<NSTAGE - 2>();
        __syncthreads();

        int nxt = it + NSTAGE - 1;
        if (nxt < KITER) load_stage(nxt % NSTAGE, nxt * 64);
        cp_commit();

        const uint32_t At = sbase + (uint32_t)((it % NSTAGE) * STAGE_B);
        const uint32_t Bt = At + 16384;

        uint32_t a0[2][4], b0[4][4];
        uint32_t a1[2][4], b1[4][4];
        frag_load(At, Bt, 0, a0, b0);
        #pragma unroll
        for (int ks = 0; ks < 4; ks++) {
            if (ks & 1) {
                if (ks < 3) frag_load(At, Bt, ks + 1, a0, b0);
                frag_mma(a1, b1);
            } else {
                frag_load(At, Bt, ks + 1 > 3 ? 3 : ks + 1, a1, b1);
                frag_mma(a0, b0);
            }
        }
    }

    #pragma unroll
    for (int mi = 0; mi < 2; mi++) {
        #pragma unroll
        for (int r2 = 0; r2 < 2; r2++) {
            int t = m0 + wm * 32 + mi * 16 + g + r2 * 8;
            #pragma unroll
            for (int ni = 0; ni < 8; ni++) {
                int col = n0 + wn * 64 + ni * 8 + tg * 2;
                float2 v;
                v.x = acc[mi][ni][r2 * 2 + 0];
                v.y = acc[mi][ni][r2 * 2 + 1];
                *(float2*)(OUT + (size_t)t * HDIM + col) = v;
            }
        }
    }
}

// ---------------------------------------------------------------------------
extern "C" void kernel_launch(void* const* d_in, const int* in_sizes, int n_in,
                              void* d_out, int out_size) {
    const float* x  = (const float*)d_in[0];
    const float* rw = (const float*)d_in[1];
    const float* gu = (const float*)d_in[2];
    const float* dw = (const float*)d_in[3];
    float* out = (float*)d_out;

    const long long OUT_ELEMS = (long long)T_TOK * HDIM;
    float* tail = nullptr;
    if ((long long)out_size >= OUT_ELEMS + (long long)T_TOK * TOPK)
        tail = out + OUT_ELEMS;

    cudaFuncSetAttribute(gemm1_kernel, cudaFuncAttributeMaxDynamicSharedMemorySize, G_SMEM);
    cudaFuncSetAttribute(gemm2_kernel, cudaFuncAttributeMaxDynamicSharedMemorySize, G_SMEM);

    tpose_rw_kernel<<<(NEXP * HDIM + 255) / 256, 256>>>(rw);
    cvt_x_kernel<<<2048, 256>>>(x);
    cvt_gu_kernel<<<8192, 256>>>(gu);
    cvt_dw_kernel<<<8192, 256>>>(dw);
    router_kernel<<<T_TOK / 8, 256>>>(x, tail);

    dim3 grid1(T_TOK / 128, IDIM / 64, TOPK);   // (32, 22, 8)
    gemm1_kernel<<<grid1, 256, G_SMEM>>>();

    dim3 grid2(HDIM / 128, T_TOK / 128);        // (16, 32), n fastest
    gemm2_kernel<<<grid2, 256, G_SMEM>>>(out);
}

// round 13
// speedup vs baseline: 1.0496x; 1.0213x over previous
#include <cuda_runtime.h>
#include <cuda_fp16.h>
#include <cstdint>

// Fixed shapes for NKIMoELayer_24970939859026
#define T_TOK 4096
#define HDIM  2048
#define NEXP  16
#define TOPK  8             // reference uses experts 0..7 densely
#define IDIM  1408
#define TWOI  2816
#define KC    (TOPK * IDIM) // 11264

// Scratch (__device__ globals: allocation-free rule)
__device__ __half g_hid[(size_t)T_TOK * KC];          // hid' fp16       [t][e*IDIM+i]
__device__ float  g_rw [T_TOK * TOPK];
__device__ float  g_rwt[NEXP * HDIM];                 // router_w^T      [e][h]
__device__ __half g_xh [(size_t)T_TOK * HDIM];        // fp16(X)         [t][h]
__device__ __half g_guh[(size_t)TOPK * HDIM * TWOI];  // fp16(gate_up)   [e][h][feat]
__device__ __half g_dwh[(size_t)KC * HDIM];           // fp16(down flat) [k][h]

__device__ __forceinline__ void mma_f16(float* c, const uint32_t* a, uint32_t b0, uint32_t b1) {
    asm volatile(
        "mma.sync.aligned.m16n8k16.row.col.f32.f16.f16.f32 "
        "{%0,%1,%2,%3}, {%4,%5,%6,%7}, {%8,%9}, {%0,%1,%2,%3};"
        : "+f"(c[0]), "+f"(c[1]), "+f"(c[2]), "+f"(c[3])
        : "r"(a[0]), "r"(a[1]), "r"(a[2]), "r"(a[3]), "r"(b0), "r"(b1));
}

__device__ __forceinline__ void ldsm4(uint32_t* r, uint32_t addr) {
    asm volatile("ldmatrix.sync.aligned.m8n8.x4.shared.b16 {%0,%1,%2,%3}, [%4];"
        : "=r"(r[0]), "=r"(r[1]), "=r"(r[2]), "=r"(r[3]) : "r"(addr));
}
__device__ __forceinline__ void ldsm4t(uint32_t* r, uint32_t addr) {
    asm volatile("ldmatrix.sync.aligned.m8n8.x4.trans.shared.b16 {%0,%1,%2,%3}, [%4];"
        : "=r"(r[0]), "=r"(r[1]), "=r"(r[2]), "=r"(r[3]) : "r"(addr));
}

__device__ __forceinline__ void cp_async16(uint32_t smem, const void* gmem) {
    asm volatile("cp.async.cg.shared.global [%0], [%1], 16;" :: "r"(smem), "l"(gmem));
}
__device__ __forceinline__ void cp_commit() { asm volatile("cp.async.commit_group;"); }
template<int N> __device__ __forceinline__ void cp_wait() {
    asm volatile("cp.async.wait_group %0;" :: "n"(N));
}

// Swizzled store offsets; chunk = 16B; chunk position ^= (row & 7) (low 3 bits).
__device__ __forceinline__ uint32_t sw128(int row, int c) {
    return (uint32_t)(row * 128 + ((c ^ (row & 7)) << 4));
}
__device__ __forceinline__ uint32_t sw256(int row, int c) {
    return (uint32_t)(row * 256 + ((c ^ (row & 7)) << 4));
}
// A-fragment ldmatrix address ([m][k] tile, 128B rows):
// lr = lane&7, hm = (lane>>3)&1 (m half), hk = lane>>4 (k chunk +0/+1).
__device__ __forceinline__ uint32_t ldsmA_addr(uint32_t tile, int rowbase, int cb,
                                               int lr, int hm, int hk) {
    int row = rowbase + hm * 8 + lr;
    return tile + (uint32_t)(row * 128) + (uint32_t)((((cb + hk) ^ (row & 7)) << 4));
}
// B-fragment (trans) addresses for [k][n] tiles (128B / 256B rows):
// kr = lane&7, nc = (lane>>3)&1 (n 8-block), kh = lane>>4 (k 8-block).
__device__ __forceinline__ uint32_t ldsmBt128(uint32_t tile, int kbase, int ncb,
                                              int kr, int nc, int kh) {
    int row = kbase + kh * 8 + kr;
    return tile + (uint32_t)(row * 128) + (uint32_t)((((ncb + nc) ^ kr) << 4));
}
__device__ __forceinline__ uint32_t ldsmBt256(uint32_t tile, int kbase, int ncb,
                                              int kr, int nc, int kh) {
    int row = kbase + kh * 8 + kr;
    return tile + (uint32_t)(row * 256) + (uint32_t)((((ncb + nc) ^ kr) << 4));
}

// ---------------------------------------------------------------------------
// Pre-pass: fp32 -> fp16 straight copies, 32B-read / 16B-store per thread.
// ---------------------------------------------------------------------------
__device__ __forceinline__ uint4 cvt8_f32_f16(float4 a, float4 b) {
    __half2 h0 = __floats2half2_rn(a.x, a.y);
    __half2 h1 = __floats2half2_rn(a.z, a.w);
    __half2 h2 = __floats2half2_rn(b.x, b.y);
    __half2 h3 = __floats2half2_rn(b.z, b.w);
    uint4 o;
    o.x = *reinterpret_cast<uint32_t*>(&h0);
    o.y = *reinterpret_cast<uint32_t*>(&h1);
    o.z = *reinterpret_cast<uint32_t*>(&h2);
    o.w = *reinterpret_cast<uint32_t*>(&h3);
    return o;
}
__global__ __launch_bounds__(256) void cvt_x_kernel(const float* __restrict__ src) {
    const long long n8 = (long long)T_TOK * HDIM / 8;
    long long i = (long long)blockIdx.x * blockDim.x + threadIdx.x;
    long long st = (long long)gridDim.x * blockDim.x;
    const float4* s4 = (const float4*)src;
    for (; i < n8; i += st)
        ((uint4*)g_xh)[i] = cvt8_f32_f16(s4[i * 2], s4[i * 2 + 1]);
}
__global__ __launch_bounds__(256) void cvt_gu_kernel(const float* __restrict__ src) {
    const long long n8 = (long long)TOPK * HDIM * TWOI / 8;
    long long i = (long long)blockIdx.x * blockDim.x + threadIdx.x;
    long long st = (long long)gridDim.x * blockDim.x;
    const float4* s4 = (const float4*)src;
    for (; i < n8; i += st)
        ((uint4*)g_guh)[i] = cvt8_f32_f16(s4[i * 2], s4[i * 2 + 1]);
}
__global__ __launch_bounds__(256) void cvt_dw_kernel(const float* __restrict__ src) {
    const long long n8 = (long long)KC * HDIM / 8;
    long long i = (long long)blockIdx.x * blockDim.x + threadIdx.x;
    long long st = (long long)gridDim.x * blockDim.x;
    const float4* s4 = (const float4*)src;
    for (; i < n8; i += st)
        ((uint4*)g_dwh)[i] = cvt8_f32_f16(s4[i * 2], s4[i * 2 + 1]);
}
// router_w[h][e] -> g_rwt[e][h]
__global__ __launch_bounds__(256) void tpose_rw_kernel(const float* __restrict__ src) {
    int i = blockIdx.x * blockDim.x + threadIdx.x;
    if (i < NEXP * HDIM) {
        int e = i / HDIM, h = i % HDIM;
        g_rwt[i] = src[h * NEXP + e];
    }
}

// ---------------------------------------------------------------------------
// Router: one warp per token; rwt gives fully coalesced weight reads.
// ---------------------------------------------------------------------------
__global__ __launch_bounds__(256) void router_kernel(
    const float* __restrict__ x, float* __restrict__ w_tail)
{
    int t = (blockIdx.x * blockDim.x + threadIdx.x) >> 5;
    int lane = threadIdx.x & 31;
    if (t >= T_TOK) return;
    const float* xr = x + (size_t)t * HDIM;

    float acc[NEXP] = {};
    for (int h0 = lane * 4; h0 < HDIM; h0 += 128) {
        float4 xv = *(const float4*)(xr + h0);
        #pragma unroll
        for (int e = 0; e < NEXP; e++) {
            float4 wv = *(const float4*)(g_rwt + e * HDIM + h0);
            acc[e] += xv.x * wv.x + xv.y * wv.y + xv.z * wv.z + xv.w * wv.w;
        }
    }
    #pragma unroll
    for (int e = 0; e < NEXP; e++) {
        #pragma unroll
        for (int o = 16; o; o >>= 1) acc[e] += __shfl_xor_sync(0xFFFFFFFFu, acc[e], o);
    }
    if (lane == 0) {
        float m = acc[0];
        #pragma unroll
        for (int e = 1; e < NEXP; e++) m = fmaxf(m, acc[e]);
        float p[NEXP];
        #pragma unroll
        for (int e = 0; e < NEXP; e++) p[e] = expf(acc[e] - m);
        float v[TOPK]; float ssel = 0.f;
        #pragma unroll
        for (int k = 0; k < TOPK; k++) {
            int bi = 0; float bv = -1.f;
            #pragma unroll
            for (int e = 0; e < NEXP; e++) if (p[e] > bv) { bv = p[e]; bi = e; }
            p[bi] = -2.f; v[k] = bv; ssel += bv;
        }
        float inv = 1.f / ssel;
        #pragma unroll
        for (int k = 0; k < TOPK; k++) {
            float wv = v[k] * inv;
            g_rw[t * TOPK + k] = wv;
            if (w_tail) w_tail[t * TOPK + k] = wv;
        }
    }
}

#define NSTAGE  3
#define STAGE_B 32768    // A 16 KB (128 rows x 128B) + B region 16 KB
#define G_SMEM  (NSTAGE * STAGE_B)

// ---------------------------------------------------------------------------
// GEMM1: hid'[t, e*IDIM+n] = w[t,e] * silu(X@GUe[:,n]) * (X@GUe[:,IDIM+n])
// BM=128, BN=64(gate)+64(up), BK=64. B tiles stored [k][n] (64 x 128B),
// fragments via ldmatrix.trans. 8 warps (4x2), warp 32x32(+32x32).
// ---------------------------------------------------------------------------
__global__ __launch_bounds__(256, 2) void gemm1_kernel()
{
    extern __shared__ __align__(128) char smem[];
    const uint32_t sbase = (uint32_t)__cvta_generic_to_shared(smem);
    const int m0 = blockIdx.x * 128;
    const int n0 = blockIdx.y * 64;
    const int e  = blockIdx.z;
    const __half* Bbase = g_guh + (size_t)e * HDIM * TWOI;   // [h][feat]

    const int tid = threadIdx.x;
    const int wid = tid >> 5, lane = tid & 31;
    const int wm = wid & 3, wn = wid >> 2;
    const int g = lane >> 2, tg = lane & 3;
    const int lr = lane & 7, hm = (lane >> 3) & 1, hk = lane >> 4;

    float accG[2][4][4] = {};
    float accU[2][4][4] = {};
    const int KITER = HDIM / 64;   // 32

    auto load_stage = [&](int s, int kk) {
        uint32_t st = sbase + (uint32_t)(s * STAGE_B);
        // A: 128 rows x 8 chunks = 1024 jobs -> 4/thread
        #pragma unroll
        for (int i = 0; i < 4; i++) {
            int idx = tid + i * 256;
            int row = idx >> 3, c = idx & 7;
            cp_async16(st + sw128(row, c), g_xh + (size_t)(m0 + row) * HDIM + kk + c * 8);
        }
        // G,U tiles [k=64][n=64]: 2 x 512 jobs -> 4/thread
        #pragma unroll
        for (int i = 0; i < 4; i++) {
            int idx = tid + i * 256;
            int up = idx >> 9;                 // 0: gate, 1: up
            int r = (idx & 511) >> 3, c = idx & 7;     // r = k row, c = n chunk
            int feat = up ? (IDIM + n0 + c * 8) : (n0 + c * 8);
            uint32_t dst = st + 16384 + (uint32_t)(up * 8192);
            cp_async16(dst + sw128(r, c), Bbase + (size_t)(kk + r) * TWOI + feat);
        }
    };

    #pragma unroll
    for (int s = 0; s < NSTAGE - 1; s++) { load_stage(s, s * 64); cp_commit(); }

    for (int it = 0; it < KITER; it++) {
        cp_wait<NSTAGE - 2>();
        __syncthreads();

        int nxt = it + NSTAGE - 1;
        if (nxt < KITER) load_stage(nxt % NSTAGE, nxt * 64);
        cp_commit();

        const uint32_t At = sbase + (uint32_t)((it % NSTAGE) * STAGE_B);
        const uint32_t Gt = At + 16384;
        const uint32_t Ut = At + 24576;

        #pragma unroll
        for (int ks = 0; ks < 4; ks++) {
            int cb = ks * 2;                      // A k-chunk base
            int kb = ks * 16;                     // B k-row base
            uint32_t a[2][4];
            #pragma unroll
            for (int mi = 0; mi < 2; mi++)
                ldsm4(a[mi], ldsmA_addr(At, wm * 32 + mi * 16, cb, lr, hm, hk));
            uint32_t bg[2][4], bu[2][4];
            #pragma unroll
            for (int p = 0; p < 2; p++) {
                int ncb = wn * 4 + p * 2;
                ldsm4t(bg[p], ldsmBt128(Gt, kb, ncb, lr, hm, hk));
                ldsm4t(bu[p], ldsmBt128(Ut, kb, ncb, lr, hm, hk));
            }
            #pragma unroll
            for (int ni = 0; ni < 4; ni++) {
                int p = ni >> 1, o = ni & 1;
                #pragma unroll
                for (int mi = 0; mi < 2; mi++) {
                    mma_f16(accG[mi][ni], a[mi], bg[p][o], bg[p][o + 2]);
                    mma_f16(accU[mi][ni], a[mi], bu[p][o], bu[p][o + 2]);
                }
            }
        }
    }

    // Epilogue: hid' = w * silu(gate) * up -> fp16
    #pragma unroll
    for (int mi = 0; mi < 2; mi++) {
        #pragma unroll
        for (int r2 = 0; r2 < 2; r2++) {
            int t = m0 + wm * 32 + mi * 16 + g + r2 * 8;
            float w = g_rw[t * TOPK + e];
            __half* dst = g_hid + (size_t)t * KC + (size_t)e * IDIM + n0;
            #pragma unroll
            for (int ni = 0; ni < 4; ni++) {
                int col = wn * 32 + ni * 8 + tg * 2;
                float gv0 = accG[mi][ni][r2 * 2 + 0], uv0 = accU[mi][ni][r2 * 2 + 0];
                float gv1 = accG[mi][ni][r2 * 2 + 1], uv1 = accU[mi][ni][r2 * 2 + 1];
                float h0 = (gv0 / (1.f + expf(-gv0))) * uv0 * w;
                float h1 = (gv1 / (1.f + expf(-gv1))) * uv1 * w;
                *(__half2*)(dst + col) = __floats2half2_rn(h0, h1);
            }
        }
    }
}

// ---------------------------------------------------------------------------
// GEMM2: out[4096,2048] = g_hid[4096,11264] @ down_flat[11264,2048]
// BM=128, BN=128, BK=64. B tile stored [k=64][n=128] (256B rows),
// fragments via ldmatrix.trans. 8 warps (4x2), warp 32x64.
// ---------------------------------------------------------------------------
__global__ __launch_bounds__(256, 2) void gemm2_kernel(float* __restrict__ OUT)
{
    extern __shared__ __align__(128) char smem[];
    const uint32_t sbase = (uint32_t)__cvta_generic_to_shared(smem);
    const int m0 = blockIdx.x * 128;
    const int n0 = blockIdx.y * 128;

    const int tid = threadIdx.x;
    const int wid = tid >> 5, lane = tid & 31;
    const int wm = wid & 3, wn = wid >> 2;
    const int g = lane >> 2, tg = lane & 3;
    const int lr = lane & 7, hm = (lane >> 3) & 1, hk = lane >> 4;

    float acc[2][8][4] = {};
    const int KITER = KC / 64;   // 176

    auto load_stage = [&](int s, int kk) {
        uint32_t st = sbase + (uint32_t)(s * STAGE_B);
        // A: 128 rows x 8 chunks
        #pragma unroll
        for (int i = 0; i < 4; i++) {
            int idx = tid + i * 256;
            int row = idx >> 3, c = idx & 7;
            cp_async16(st + sw128(row, c), g_hid + (size_t)(m0 + row) * KC + kk + c * 8);
        }
        // B tile [k=64][n=128]: 64 rows x 16 chunks = 1024 jobs
        #pragma unroll
        for (int i = 0; i < 4; i++) {
            int idx = tid + i * 256;
            int r = idx >> 4, c = idx & 15;
            cp_async16(st + 16384 + sw256(r, c),
                       g_dwh + (size_t)(kk + r) * HDIM + n0 + c * 8);
        }
    };

    #pragma unroll
    for (int s = 0; s < NSTAGE - 1; s++) { load_stage(s, s * 64); cp_commit(); }

    for (int it = 0; it < KITER; it++) {
        cp_wait<NSTAGE - 2>();
        __syncthreads();

        int nxt = it + NSTAGE - 1;
        if (nxt < KITER) load_stage(nxt % NSTAGE, nxt * 64);
        cp_commit();

        const uint32_t At = sbase + (uint32_t)((it % NSTAGE) * STAGE_B);
        const uint32_t Bt = At + 16384;

        #pragma unroll
        for (int ks = 0; ks < 4; ks++) {
            int cb = ks * 2;
            int kb = ks * 16;
            uint32_t a[2][4];
            #pragma unroll
            for (int mi = 0; mi < 2; mi++)
                ldsm4(a[mi], ldsmA_addr(At, wm * 32 + mi * 16, cb, lr, hm, hk));
            uint32_t b[4][4];
            #pragma unroll
            for (int p = 0; p < 4; p++) {
                int ncb = wn * 8 + p * 2;
                ldsm4t(b[p], ldsmBt256(Bt, kb, ncb, lr, hm, hk));
            }
            #pragma unroll
            for (int ni = 0; ni < 8; ni++) {
                int p = ni >> 1, o = ni & 1;
                #pragma unroll
                for (int mi = 0; mi < 2; mi++)
                    mma_f16(acc[mi][ni], a[mi], b[p][o], b[p][o + 2]);
            }
        }
    }

    #pragma unroll
    for (int mi = 0; mi < 2; mi++) {
        #pragma unroll
        for (int r2 = 0; r2 < 2; r2++) {
            int t = m0 + wm * 32 + mi * 16 + g + r2 * 8;
            #pragma unroll
            for (int ni = 0; ni < 8; ni++) {
                int col = n0 + wn * 64 + ni * 8 + tg * 2;
                float2 v;
                v.x = acc[mi][ni][r2 * 2 + 0];
                v.y = acc[mi][ni][r2 * 2 + 1];
                *(float2*)(OUT + (size_t)t * HDIM + col) = v;
            }
        }
    }
}

// ---------------------------------------------------------------------------
extern "C" void kernel_launch(void* const* d_in, const int* in_sizes, int n_in,
                              void* d_out, int out_size) {
    const float* x  = (const float*)d_in[0];
    const float* rw = (const float*)d_in[1];
    const float* gu = (const float*)d_in[2];
    const float* dw = (const float*)d_in[3];
    float* out = (float*)d_out;

    const long long OUT_ELEMS = (long long)T_TOK * HDIM;
    float* tail = nullptr;
    if ((long long)out_size >= OUT_ELEMS + (long long)T_TOK * TOPK)
        tail = out + OUT_ELEMS;

    cudaFuncSetAttribute(gemm1_kernel, cudaFuncAttributeMaxDynamicSharedMemorySize, G_SMEM);
    cudaFuncSetAttribute(gemm2_kernel, cudaFuncAttributeMaxDynamicSharedMemorySize, G_SMEM);

    tpose_rw_kernel<<<(NEXP * HDIM + 255) / 256, 256>>>(rw);
    cvt_x_kernel<<<2048, 256>>>(x);
    cvt_gu_kernel<<<8192, 256>>>(gu);
    cvt_dw_kernel<<<8192, 256>>>(dw);
    router_kernel<<<T_TOK / 8, 256>>>(x, tail);

    dim3 grid1(T_TOK / 128, IDIM / 64, TOPK);   // (32, 22, 8)
    gemm1_kernel<<<grid1, 256, G_SMEM>>>();

    dim3 grid2(T_TOK / 128, HDIM / 128);        // (32, 16)
    gemm2_kernel<<<grid2, 256, G_SMEM>>>(out);
}

// round 14
// speedup vs baseline: 1.0624x; 1.0122x over previous
#include <cuda_runtime.h>
#include <cuda_fp16.h>
#include <cstdint>

// Fixed shapes for NKIMoELayer_24970939859026
#define T_TOK 4096
#define HDIM  2048
#define NEXP  16
#define TOPK  8             // reference uses experts 0..7 densely
#define IDIM  1408
#define TWOI  2816
#define KC    (TOPK * IDIM) // 11264

// Scratch (__device__ globals: allocation-free rule)
__device__ __half g_hid[(size_t)T_TOK * KC];          // hid' fp16       [t][e*IDIM+i]
__device__ float  g_rw [T_TOK * TOPK];
__device__ float  g_rwt[NEXP * HDIM];                 // router_w^T      [e][h]
__device__ __half g_xh [(size_t)T_TOK * HDIM];        // fp16(X)         [t][h]
__device__ __half g_guh[(size_t)TOPK * HDIM * TWOI];  // fp16(gate_up)   [e][h][feat]
__device__ __half g_dwh[(size_t)KC * HDIM];           // fp16(down flat) [k][h]

__device__ __forceinline__ void mma_f16(float* c, const uint32_t* a, uint32_t b0, uint32_t b1) {
    asm volatile(
        "mma.sync.aligned.m16n8k16.row.col.f32.f16.f16.f32 "
        "{%0,%1,%2,%3}, {%4,%5,%6,%7}, {%8,%9}, {%0,%1,%2,%3};"
        : "+f"(c[0]), "+f"(c[1]), "+f"(c[2]), "+f"(c[3])
        : "r"(a[0]), "r"(a[1]), "r"(a[2]), "r"(a[3]), "r"(b0), "r"(b1));
}

__device__ __forceinline__ void ldsm4(uint32_t* r, uint32_t addr) {
    asm volatile("ldmatrix.sync.aligned.m8n8.x4.shared.b16 {%0,%1,%2,%3}, [%4];"
        : "=r"(r[0]), "=r"(r[1]), "=r"(r[2]), "=r"(r[3]) : "r"(addr));
}
__device__ __forceinline__ void ldsm4t(uint32_t* r, uint32_t addr) {
    asm volatile("ldmatrix.sync.aligned.m8n8.x4.trans.shared.b16 {%0,%1,%2,%3}, [%4];"
        : "=r"(r[0]), "=r"(r[1]), "=r"(r[2]), "=r"(r[3]) : "r"(addr));
}

__device__ __forceinline__ void cp_async16(uint32_t smem, const void* gmem) {
    asm volatile("cp.async.cg.shared.global [%0], [%1], 16;" :: "r"(smem), "l"(gmem));
}
__device__ __forceinline__ void cp_commit() { asm volatile("cp.async.commit_group;"); }
template<int N> __device__ __forceinline__ void cp_wait() {
    asm volatile("cp.async.wait_group %0;" :: "n"(N));
}

// Swizzled store offsets; chunk = 16B; chunk position ^= (row & 7) (low 3 bits).
__device__ __forceinline__ uint32_t sw128(int row, int c) {
    return (uint32_t)(row * 128 + ((c ^ (row & 7)) << 4));
}
__device__ __forceinline__ uint32_t sw256(int row, int c) {
    return (uint32_t)(row * 256 + ((c ^ (row & 7)) << 4));
}
// A-fragment ldmatrix address ([m][k] tile, 128B rows):
// lr = lane&7, hm = (lane>>3)&1 (m half), hk = lane>>4 (k chunk +0/+1).
__device__ __forceinline__ uint32_t ldsmA_addr(uint32_t tile, int rowbase, int cb,
                                               int lr, int hm, int hk) {
    int row = rowbase + hm * 8 + lr;
    return tile + (uint32_t)(row * 128) + (uint32_t)((((cb + hk) ^ (row & 7)) << 4));
}
// B-fragment (trans) addresses for [k][n] tiles (128B / 256B rows):
// kr = lane&7, nc = (lane>>3)&1 (n 8-block), kh = lane>>4 (k 8-block).
__device__ __forceinline__ uint32_t ldsmBt128(uint32_t tile, int kbase, int ncb,
                                              int kr, int nc, int kh) {
    int row = kbase + kh * 8 + kr;
    return tile + (uint32_t)(row * 128) + (uint32_t)((((ncb + nc) ^ kr) << 4));
}
__device__ __forceinline__ uint32_t ldsmBt256(uint32_t tile, int kbase, int ncb,
                                              int kr, int nc, int kh) {
    int row = kbase + kh * 8 + kr;
    return tile + (uint32_t)(row * 256) + (uint32_t)((((ncb + nc) ^ kr) << 4));
}

// ---------------------------------------------------------------------------
// Fused pre-pass: fp32 -> fp16 for gate_up, down, X in ONE kernel.
// 32B-read / 16B-store per thread, grid-stride over the concatenated range.
// ---------------------------------------------------------------------------
__device__ __forceinline__ uint4 cvt8_f32_f16(float4 a, float4 b) {
    __half2 h0 = __floats2half2_rn(a.x, a.y);
    __half2 h1 = __floats2half2_rn(a.z, a.w);
    __half2 h2 = __floats2half2_rn(b.x, b.y);
    __half2 h3 = __floats2half2_rn(b.z, b.w);
    uint4 o;
    o.x = *reinterpret_cast<uint32_t*>(&h0);
    o.y = *reinterpret_cast<uint32_t*>(&h1);
    o.z = *reinterpret_cast<uint32_t*>(&h2);
    o.w = *reinterpret_cast<uint32_t*>(&h3);
    return o;
}
#define N_GU ((long long)TOPK * HDIM * TWOI / 8)   // 5,767,168 uint4 jobs
#define N_DW ((long long)KC * HDIM / 8)            // 2,883,584
#define N_X  ((long long)T_TOK * HDIM / 8)         // 1,048,576
#define N_ALL (N_GU + N_DW + N_X)

__global__ __launch_bounds__(256) void cvt_all_kernel(
    const float* __restrict__ gu, const float* __restrict__ dw,
    const float* __restrict__ x)
{
    long long i = (long long)blockIdx.x * blockDim.x + threadIdx.x;
    long long st = (long long)gridDim.x * blockDim.x;
    for (; i < N_ALL; i += st) {
        const float4* s;
        uint4* d;
        long long j = i;
        if (j < N_GU) {
            s = (const float4*)gu;  d = (uint4*)g_guh;
        } else if (j < N_GU + N_DW) {
            j -= N_GU;
            s = (const float4*)dw;  d = (uint4*)g_dwh;
        } else {
            j -= N_GU + N_DW;
            s = (const float4*)x;   d = (uint4*)g_xh;
        }
        d[j] = cvt8_f32_f16(s[j * 2], s[j * 2 + 1]);
    }
}
// router_w[h][e] -> g_rwt[e][h]
__global__ __launch_bounds__(256) void tpose_rw_kernel(const float* __restrict__ src) {
    int i = blockIdx.x * blockDim.x + threadIdx.x;
    if (i < NEXP * HDIM) {
        int e = i / HDIM, h = i % HDIM;
        g_rwt[i] = src[h * NEXP + e];
    }
}

// ---------------------------------------------------------------------------
// Router: one warp per token; rwt gives fully coalesced weight reads.
// ---------------------------------------------------------------------------
__global__ __launch_bounds__(256) void router_kernel(
    const float* __restrict__ x, float* __restrict__ w_tail)
{
    int t = (blockIdx.x * blockDim.x + threadIdx.x) >> 5;
    int lane = threadIdx.x & 31;
    if (t >= T_TOK) return;
    const float* xr = x + (size_t)t * HDIM;

    float acc[NEXP] = {};
    for (int h0 = lane * 4; h0 < HDIM; h0 += 128) {
        float4 xv = *(const float4*)(xr + h0);
        #pragma unroll
        for (int e = 0; e < NEXP; e++) {
            float4 wv = *(const float4*)(g_rwt + e * HDIM + h0);
            acc[e] += xv.x * wv.x + xv.y * wv.y + xv.z * wv.z + xv.w * wv.w;
        }
    }
    #pragma unroll
    for (int e = 0; e < NEXP; e++) {
        #pragma unroll
        for (int o = 16; o; o >>= 1) acc[e] += __shfl_xor_sync(0xFFFFFFFFu, acc[e], o);
    }
    if (lane == 0) {
        float m = acc[0];
        #pragma unroll
        for (int e = 1; e < NEXP; e++) m = fmaxf(m, acc[e]);
        float p[NEXP];
        #pragma unroll
        for (int e = 0; e < NEXP; e++) p[e] = expf(acc[e] - m);
        float v[TOPK]; float ssel = 0.f;
        #pragma unroll
        for (int k = 0; k < TOPK; k++) {
            int bi = 0; float bv = -1.f;
            #pragma unroll
            for (int e = 0; e < NEXP; e++) if (p[e] > bv) { bv = p[e]; bi = e; }
            p[bi] = -2.f; v[k] = bv; ssel += bv;
        }
        float inv = 1.f / ssel;
        #pragma unroll
        for (int k = 0; k < TOPK; k++) {
            float wv = v[k] * inv;
            g_rw[t * TOPK + k] = wv;
            if (w_tail) w_tail[t * TOPK + k] = wv;
        }
    }
}

#define NSTAGE  3
#define STAGE_B 32768    // A 16 KB (128 rows x 128B) + B region 16 KB
#define G_SMEM  (NSTAGE * STAGE_B)

// ---------------------------------------------------------------------------
// GEMM1: hid'[t, e*IDIM+n] = w[t,e] * silu(X@GUe[:,n]) * (X@GUe[:,IDIM+n])
// BM=128, BN=64(gate)+64(up), BK=64. B tiles stored [k][n] (64 x 128B),
// fragments via ldmatrix.trans. 8 warps (4x2), warp 32x32(+32x32).
// ---------------------------------------------------------------------------
__global__ __launch_bounds__(256, 2) void gemm1_kernel()
{
    extern __shared__ __align__(128) char smem[];
    const uint32_t sbase = (uint32_t)__cvta_generic_to_shared(smem);
    const int m0 = blockIdx.x * 128;
    const int n0 = blockIdx.y * 64;
    const int e  = blockIdx.z;
    const __half* Bbase = g_guh + (size_t)e * HDIM * TWOI;   // [h][feat]

    const int tid = threadIdx.x;
    const int wid = tid >> 5, lane = tid & 31;
    const int wm = wid & 3, wn = wid >> 2;
    const int g = lane >> 2, tg = lane & 3;
    const int lr = lane & 7, hm = (lane >> 3) & 1, hk = lane >> 4;

    float accG[2][4][4] = {};
    float accU[2][4][4] = {};
    const int KITER = HDIM / 64;   // 32

    auto load_stage = [&](int s, int kk) {
        uint32_t st = sbase + (uint32_t)(s * STAGE_B);
        // A: 128 rows x 8 chunks = 1024 jobs -> 4/thread
        #pragma unroll
        for (int i = 0; i < 4; i++) {
            int idx = tid + i * 256;
            int row = idx >> 3, c = idx & 7;
            cp_async16(st + sw128(row, c), g_xh + (size_t)(m0 + row) * HDIM + kk + c * 8);
        }
        // G,U tiles [k=64][n=64]: 2 x 512 jobs -> 4/thread
        #pragma unroll
        for (int i = 0; i < 4; i++) {
            int idx = tid + i * 256;
            int up = idx >> 9;                 // 0: gate, 1: up
            int r = (idx & 511) >> 3, c = idx & 7;     // r = k row, c = n chunk
            int feat = up ? (IDIM + n0 + c * 8) : (n0 + c * 8);
            uint32_t dst = st + 16384 + (uint32_t)(up * 8192);
            cp_async16(dst + sw128(r, c), Bbase + (size_t)(kk + r) * TWOI + feat);
        }
    };

    #pragma unroll
    for (int s = 0; s < NSTAGE - 1; s++) { load_stage(s, s * 64); cp_commit(); }

    for (int it = 0; it < KITER; it++) {
        cp_wait<NSTAGE - 2>();
        __syncthreads();

        int nxt = it + NSTAGE - 1;
        if (nxt < KITER) load_stage(nxt % NSTAGE, nxt * 64);
        cp_commit();

        const uint32_t At = sbase + (uint32_t)((it % NSTAGE) * STAGE_B);
        const uint32_t Gt = At + 16384;
        const uint32_t Ut = At + 24576;

        #pragma unroll
        for (int ks = 0; ks < 4; ks++) {
            int cb = ks * 2;                      // A k-chunk base
            int kb = ks * 16;                     // B k-row base
            uint32_t a[2][4];
            #pragma unroll
            for (int mi = 0; mi < 2; mi++)
                ldsm4(a[mi], ldsmA_addr(At, wm * 32 + mi * 16, cb, lr, hm, hk));
            uint32_t bg[2][4], bu[2][4];
            #pragma unroll
            for (int p = 0; p < 2; p++) {
                int ncb = wn * 4 + p * 2;
                ldsm4t(bg[p], ldsmBt128(Gt, kb, ncb, lr, hm, hk));
                ldsm4t(bu[p], ldsmBt128(Ut, kb, ncb, lr, hm, hk));
            }
            #pragma unroll
            for (int ni = 0; ni < 4; ni++) {
                int p = ni >> 1, o = ni & 1;
                #pragma unroll
                for (int mi = 0; mi < 2; mi++) {
                    mma_f16(accG[mi][ni], a[mi], bg[p][o], bg[p][o + 2]);
                    mma_f16(accU[mi][ni], a[mi], bu[p][o], bu[p][o + 2]);
                }
            }
        }
    }

    // Epilogue: hid' = w * silu(gate) * up -> fp16
    #pragma unroll
    for (int mi = 0; mi < 2; mi++) {
        #pragma unroll
        for (int r2 = 0; r2 < 2; r2++) {
            int t = m0 + wm * 32 + mi * 16 + g + r2 * 8;
            float w = g_rw[t * TOPK + e];
            __half* dst = g_hid + (size_t)t * KC + (size_t)e * IDIM + n0;
            #pragma unroll
            for (int ni = 0; ni < 4; ni++) {
                int col = wn * 32 + ni * 8 + tg * 2;
                float gv0 = accG[mi][ni][r2 * 2 + 0], uv0 = accU[mi][ni][r2 * 2 + 0];
                float gv1 = accG[mi][ni][r2 * 2 + 1], uv1 = accU[mi][ni][r2 * 2 + 1];
                float h0 = (gv0 / (1.f + expf(-gv0))) * uv0 * w;
                float h1 = (gv1 / (1.f + expf(-gv1))) * uv1 * w;
                *(__half2*)(dst + col) = __floats2half2_rn(h0, h1);
            }
        }
    }
}

// ---------------------------------------------------------------------------
// GEMM2: out[4096,2048] = g_hid[4096,11264] @ down_flat[11264,2048]
// BM=128, BN=128, BK=64. B tile stored [k=64][n=128] (256B rows),
// fragments via ldmatrix.trans. 8 warps (4x2), warp 32x64.
// ---------------------------------------------------------------------------
__global__ __launch_bounds__(256, 2) void gemm2_kernel(float* __restrict__ OUT)
{
    extern __shared__ __align__(128) char smem[];
    const uint32_t sbase = (uint32_t)__cvta_generic_to_shared(smem);
    const int m0 = blockIdx.x * 128;
    const int n0 = blockIdx.y * 128;

    const int tid = threadIdx.x;
    const int wid = tid >> 5, lane = tid & 31;
    const int wm = wid & 3, wn = wid >> 2;
    const int g = lane >> 2, tg = lane & 3;
    const int lr = lane & 7, hm = (lane >> 3) & 1, hk = lane >> 4;

    float acc[2][8][4] = {};
    const int KITER = KC / 64;   // 176

    auto load_stage = [&](int s, int kk) {
        uint32_t st = sbase + (uint32_t)(s * STAGE_B);
        // A: 128 rows x 8 chunks
        #pragma unroll
        for (int i = 0; i < 4; i++) {
            int idx = tid + i * 256;
            int row = idx >> 3, c = idx & 7;
            cp_async16(st + sw128(row, c), g_hid + (size_t)(m0 + row) * KC + kk + c * 8);
        }
        // B tile [k=64][n=128]: 64 rows x 16 chunks = 1024 jobs
        #pragma unroll
        for (int i = 0; i < 4; i++) {
            int idx = tid + i * 256;
            int r = idx >> 4, c = idx & 15;
            cp_async16(st + 16384 + sw256(r, c),
                       g_dwh + (size_t)(kk + r) * HDIM + n0 + c * 8);
        }
    };

    #pragma unroll
    for (int s = 0; s < NSTAGE - 1; s++) { load_stage(s, s * 64); cp_commit(); }

    for (int it = 0; it < KITER; it++) {
        cp_wait<NSTAGE - 2>();
        __syncthreads();

        int nxt = it + NSTAGE - 1;
        if (nxt < KITER) load_stage(nxt % NSTAGE, nxt * 64);
        cp_commit();

        const uint32_t At = sbase + (uint32_t)((it % NSTAGE) * STAGE_B);
        const uint32_t Bt = At + 16384;

        #pragma unroll
        for (int ks = 0; ks < 4; ks++) {
            int cb = ks * 2;
            int kb = ks * 16;
            uint32_t a[2][4];
            #pragma unroll
            for (int mi = 0; mi < 2; mi++)
                ldsm4(a[mi], ldsmA_addr(At, wm * 32 + mi * 16, cb, lr, hm, hk));
            uint32_t b[4][4];
            #pragma unroll
            for (int p = 0; p < 4; p++) {
                int ncb = wn * 8 + p * 2;
                ldsm4t(b[p], ldsmBt256(Bt, kb, ncb, lr, hm, hk));
            }
            #pragma unroll
            for (int ni = 0; ni < 8; ni++) {
                int p = ni >> 1, o = ni & 1;
                #pragma unroll
                for (int mi = 0; mi < 2; mi++)
                    mma_f16(acc[mi][ni], a[mi], b[p][o], b[p][o + 2]);
            }
        }
    }

    #pragma unroll
    for (int mi = 0; mi < 2; mi++) {
        #pragma unroll
        for (int r2 = 0; r2 < 2; r2++) {
            int t = m0 + wm * 32 + mi * 16 + g + r2 * 8;
            #pragma unroll
            for (int ni = 0; ni < 8; ni++) {
                int col = n0 + wn * 64 + ni * 8 + tg * 2;
                float2 v;
                v.x = acc[mi][ni][r2 * 2 + 0];
                v.y = acc[mi][ni][r2 * 2 + 1];
                *(float2*)(OUT + (size_t)t * HDIM + col) = v;
            }
        }
    }
}

// ---------------------------------------------------------------------------
extern "C" void kernel_launch(void* const* d_in, const int* in_sizes, int n_in,
                              void* d_out, int out_size) {
    const float* x  = (const float*)d_in[0];
    const float* rw = (const float*)d_in[1];
    const float* gu = (const float*)d_in[2];
    const float* dw = (const float*)d_in[3];
    float* out = (float*)d_out;

    const long long OUT_ELEMS = (long long)T_TOK * HDIM;
    float* tail = nullptr;
    if ((long long)out_size >= OUT_ELEMS + (long long)T_TOK * TOPK)
        tail = out + OUT_ELEMS;

    cudaFuncSetAttribute(gemm1_kernel, cudaFuncAttributeMaxDynamicSharedMemorySize, G_SMEM);
    cudaFuncSetAttribute(gemm2_kernel, cudaFuncAttributeMaxDynamicSharedMemorySize, G_SMEM);

    tpose_rw_kernel<<<(NEXP * HDIM + 255) / 256, 256>>>(rw);
    router_kernel<<<T_TOK / 8, 256>>>(x, tail);
    cvt_all_kernel<<<9472, 256>>>(gu, dw, x);

    dim3 grid1(T_TOK / 128, IDIM / 64, TOPK);   // (32, 22, 8)
    gemm1_kernel<<<grid1, 256, G_SMEM>>>();

    dim3 grid2(T_TOK / 128, HDIM / 128);        // (32, 16)
    gemm2_kernel<<<grid2, 256, G_SMEM>>>(out);
}

// round 15
// speedup vs baseline: 1.0939x; 1.0296x over previous
#include <cuda_runtime.h>
#include <cuda_fp16.h>
#include <cstdint>

// Fixed shapes for NKIMoELayer_24970939859026
#define T_TOK 4096
#define HDIM  2048
#define NEXP  16
#define TOPK  8             // reference uses experts 0..7 densely
#define IDIM  1408
#define TWOI  2816
#define KC    (TOPK * IDIM) // 11264

// Scratch (__device__ globals: allocation-free rule)
__device__ __half g_hid[(size_t)T_TOK * KC];          // hid' fp16       [t][e*IDIM+i]
__device__ float  g_rw [T_TOK * TOPK];
__device__ float  g_rwt[NEXP * HDIM];                 // router_w^T      [e][h]
__device__ __half g_xh [(size_t)T_TOK * HDIM];        // fp16(X)         [t][h]
__device__ __half g_guh[(size_t)TOPK * HDIM * TWOI];  // fp16(gate_up)   [e][h][feat]
__device__ __half g_dwh[(size_t)KC * HDIM];           // fp16(down flat) [k][h]

__device__ __forceinline__ void mma_f16(float* c, const uint32_t* a, uint32_t b0, uint32_t b1) {
    asm volatile(
        "mma.sync.aligned.m16n8k16.row.col.f32.f16.f16.f32 "
        "{%0,%1,%2,%3}, {%4,%5,%6,%7}, {%8,%9}, {%0,%1,%2,%3};"
        : "+f"(c[0]), "+f"(c[1]), "+f"(c[2]), "+f"(c[3])
        : "r"(a[0]), "r"(a[1]), "r"(a[2]), "r"(a[3]), "r"(b0), "r"(b1));
}

__device__ __forceinline__ void ldsm4(uint32_t* r, uint32_t addr) {
    asm volatile("ldmatrix.sync.aligned.m8n8.x4.shared.b16 {%0,%1,%2,%3}, [%4];"
        : "=r"(r[0]), "=r"(r[1]), "=r"(r[2]), "=r"(r[3]) : "r"(addr));
}
__device__ __forceinline__ void ldsm4t(uint32_t* r, uint32_t addr) {
    asm volatile("ldmatrix.sync.aligned.m8n8.x4.trans.shared.b16 {%0,%1,%2,%3}, [%4];"
        : "=r"(r[0]), "=r"(r[1]), "=r"(r[2]), "=r"(r[3]) : "r"(addr));
}

__device__ __forceinline__ void cp_async16(uint32_t smem, const void* gmem) {
    asm volatile("cp.async.cg.shared.global [%0], [%1], 16;" :: "r"(smem), "l"(gmem));
}
__device__ __forceinline__ void cp_commit() { asm volatile("cp.async.commit_group;"); }
template<int N> __device__ __forceinline__ void cp_wait() {
    asm volatile("cp.async.wait_group %0;" :: "n"(N));
}

// Swizzled store offsets; chunk = 16B; chunk position ^= (row & 7) (low 3 bits).
__device__ __forceinline__ uint32_t sw128(int row, int c) {
    return (uint32_t)(row * 128 + ((c ^ (row & 7)) << 4));
}
__device__ __forceinline__ uint32_t sw256(int row, int c) {
    return (uint32_t)(row * 256 + ((c ^ (row & 7)) << 4));
}
// A-fragment ldmatrix base address ([m][k] tile, 128B rows), ks=0:
// lr = lane&7, hm = (lane>>3)&1 (m half), hk = lane>>4 (k chunk +0/+1).
// Per ks: addr ^= (ks<<5)  [chunk = (2ks|hk)^(row&7); 2ks bits disjoint from hk]
__device__ __forceinline__ uint32_t ldsmA_base(uint32_t tile, int rowbase,
                                               int lr, int hm, int hk) {
    int row = rowbase + hm * 8 + lr;
    return tile + (uint32_t)(row * 128) + (uint32_t)(((hk ^ (row & 7)) << 4));
}
// B-fragment (trans) base address for [k][n] tiles, kbase=0:
// kr = lane&7, nc = (lane>>3)&1 (n 8-block), kh = lane>>4 (k 8-block).
// Per ks: addr += ks*16*rowbytes (pure row advance).
__device__ __forceinline__ uint32_t ldsmBt_base(uint32_t tile, int rowbytes, int ncb,
                                                int kr, int nc, int kh) {
    int row = kh * 8 + kr;
    return tile + (uint32_t)(row * rowbytes) + (uint32_t)((((ncb + nc) ^ kr) << 4));
}

// ---------------------------------------------------------------------------
// Fused pre-pass: fp32 -> fp16 for gate_up, down, X in ONE kernel.
// ---------------------------------------------------------------------------
__device__ __forceinline__ uint4 cvt8_f32_f16(float4 a, float4 b) {
    __half2 h0 = __floats2half2_rn(a.x, a.y);
    __half2 h1 = __floats2half2_rn(a.z, a.w);
    __half2 h2 = __floats2half2_rn(b.x, b.y);
    __half2 h3 = __floats2half2_rn(b.z, b.w);
    uint4 o;
    o.x = *reinterpret_cast<uint32_t*>(&h0);
    o.y = *reinterpret_cast<uint32_t*>(&h1);
    o.z = *reinterpret_cast<uint32_t*>(&h2);
    o.w = *reinterpret_cast<uint32_t*>(&h3);
    return o;
}
#define N_GU ((long long)TOPK * HDIM * TWOI / 8)
#define N_DW ((long long)KC * HDIM / 8)
#define N_X  ((long long)T_TOK * HDIM / 8)
#define N_ALL (N_GU + N_DW + N_X)

__global__ __launch_bounds__(256) void cvt_all_kernel(
    const float* __restrict__ gu, const float* __restrict__ dw,
    const float* __restrict__ x)
{
    long long i = (long long)blockIdx.x * blockDim.x + threadIdx.x;
    long long st = (long long)gridDim.x * blockDim.x;
    for (; i < N_ALL; i += st) {
        const float4* s;
        uint4* d;
        long long j = i;
        if (j < N_GU) {
            s = (const float4*)gu;  d = (uint4*)g_guh;
        } else if (j < N_GU + N_DW) {
            j -= N_GU;
            s = (const float4*)dw;  d = (uint4*)g_dwh;
        } else {
            j -= N_GU + N_DW;
            s = (const float4*)x;   d = (uint4*)g_xh;
        }
        d[j] = cvt8_f32_f16(s[j * 2], s[j * 2 + 1]);
    }
}
// router_w[h][e] -> g_rwt[e][h]
__global__ __launch_bounds__(256) void tpose_rw_kernel(const float* __restrict__ src) {
    int i = blockIdx.x * blockDim.x + threadIdx.x;
    if (i < NEXP * HDIM) {
        int e = i / HDIM, h = i % HDIM;
        g_rwt[i] = src[h * NEXP + e];
    }
}

// ---------------------------------------------------------------------------
// Router: one warp per token; rwt gives fully coalesced weight reads.
// ---------------------------------------------------------------------------
__global__ __launch_bounds__(256) void router_kernel(
    const float* __restrict__ x, float* __restrict__ w_tail)
{
    int t = (blockIdx.x * blockDim.x + threadIdx.x) >> 5;
    int lane = threadIdx.x & 31;
    if (t >= T_TOK) return;
    const float* xr = x + (size_t)t * HDIM;

    float acc[NEXP] = {};
    for (int h0 = lane * 4; h0 < HDIM; h0 += 128) {
        float4 xv = *(const float4*)(xr + h0);
        #pragma unroll
        for (int e = 0; e < NEXP; e++) {
            float4 wv = *(const float4*)(g_rwt + e * HDIM + h0);
            acc[e] += xv.x * wv.x + xv.y * wv.y + xv.z * wv.z + xv.w * wv.w;
        }
    }
    #pragma unroll
    for (int e = 0; e < NEXP; e++) {
        #pragma unroll
        for (int o = 16; o; o >>= 1) acc[e] += __shfl_xor_sync(0xFFFFFFFFu, acc[e], o);
    }
    if (lane == 0) {
        float m = acc[0];
        #pragma unroll
        for (int e = 1; e < NEXP; e++) m = fmaxf(m, acc[e]);
        float p[NEXP];
        #pragma unroll
        for (int e = 0; e < NEXP; e++) p[e] = expf(acc[e] - m);
        float v[TOPK]; float ssel = 0.f;
        #pragma unroll
        for (int k = 0; k < TOPK; k++) {
            int bi = 0; float bv = -1.f;
            #pragma unroll
            for (int e = 0; e < NEXP; e++) if (p[e] > bv) { bv = p[e]; bi = e; }
            p[bi] = -2.f; v[k] = bv; ssel += bv;
        }
        float inv = 1.f / ssel;
        #pragma unroll
        for (int k = 0; k < TOPK; k++) {
            float wv = v[k] * inv;
            g_rw[t * TOPK + k] = wv;
            if (w_tail) w_tail[t * TOPK + k] = wv;
        }
    }
}

#define NSTAGE  3
#define STAGE_B 32768    // A 16 KB (128 rows x 128B) + B region 16 KB
#define G_SMEM  (NSTAGE * STAGE_B)

// ---------------------------------------------------------------------------
// GEMM1: hid'[t, e*IDIM+n] = w[t,e] * silu(X@GUe[:,n]) * (X@GUe[:,IDIM+n])
// BM=128, BN=64(gate)+64(up), BK=64. B tiles [k][n] (64 x 128B), ldmatrix.trans.
// 8 warps (4x2), warp 32x32(+32x32). Strength-reduced mainloop addressing.
// ---------------------------------------------------------------------------
__global__ __launch_bounds__(256, 2) void gemm1_kernel()
{
    extern __shared__ __align__(128) char smem[];
    const uint32_t sbase = (uint32_t)__cvta_generic_to_shared(smem);
    const int m0 = blockIdx.x * 128;
    const int n0 = blockIdx.y * 64;
    const int e  = blockIdx.z;
    const __half* Bbase = g_guh + (size_t)e * HDIM * TWOI;   // [h][feat]

    const int tid = threadIdx.x;
    const int wid = tid >> 5, lane = tid & 31;
    const int wm = wid & 3, wn = wid >> 2;
    const int g = lane >> 2, tg = lane & 3;
    const int lr = lane & 7, hm = (lane >> 3) & 1, hk = lane >> 4;

    float accG[2][4][4] = {};
    float accU[2][4][4] = {};
    const int KITER = HDIM / 64;   // 32

    auto load_stage = [&](uint32_t soff, int kk) {
        uint32_t st = sbase + soff;
        #pragma unroll
        for (int i = 0; i < 4; i++) {
            int idx = tid + i * 256;
            int row = idx >> 3, c = idx & 7;
            cp_async16(st + sw128(row, c), g_xh + (size_t)(m0 + row) * HDIM + kk + c * 8);
        }
        #pragma unroll
        for (int i = 0; i < 4; i++) {
            int idx = tid + i * 256;
            int up = idx >> 9;                 // 0: gate, 1: up
            int r = (idx & 511) >> 3, c = idx & 7;
            int feat = up ? (IDIM + n0 + c * 8) : (n0 + c * 8);
            uint32_t dst = st + 16384 + (uint32_t)(up * 8192);
            cp_async16(dst + sw128(r, c), Bbase + (size_t)(kk + r) * TWOI + feat);
        }
    };

    #pragma unroll
    for (int s = 0; s < NSTAGE - 1; s++) { load_stage((uint32_t)(s * STAGE_B), s * 64); cp_commit(); }

    // Per-thread ldsm base addresses (stage 0, ks 0)
    uint32_t aB[2], bgB[2], buB[2];
    #pragma unroll
    for (int mi = 0; mi < 2; mi++)
        aB[mi] = ldsmA_base(sbase, wm * 32 + mi * 16, lr, hm, hk);
    #pragma unroll
    for (int p = 0; p < 2; p++) {
        bgB[p] = ldsmBt_base(sbase + 16384, 128, wn * 4 + p * 2, lr, hm, hk);
        buB[p] = ldsmBt_base(sbase + 24576, 128, wn * 4 + p * 2, lr, hm, hk);
    }

    uint32_t cons = 0, prod = (uint32_t)((NSTAGE - 1) * STAGE_B);
    for (int it = 0; it < KITER; it++) {
        cp_wait<NSTAGE - 2>();
        __syncthreads();

        int nxt = it + NSTAGE - 1;
        if (nxt < KITER) load_stage(prod, nxt * 64);
        cp_commit();
        prod += STAGE_B; if (prod == (uint32_t)(NSTAGE * STAGE_B)) prod = 0;

        #pragma unroll
        for (int ks = 0; ks < 4; ks++) {
            const uint32_t axor = (uint32_t)(ks << 5);
            const uint32_t brow = (uint32_t)(ks * 2048);   // 16 rows * 128B
            uint32_t a[2][4];
            #pragma unroll
            for (int mi = 0; mi < 2; mi++)
                ldsm4(a[mi], (aB[mi] + cons) ^ axor);
            uint32_t bg[2][4], bu[2][4];
            #pragma unroll
            for (int p = 0; p < 2; p++) {
                ldsm4t(bg[p], bgB[p] + cons + brow);
                ldsm4t(bu[p], buB[p] + cons + brow);
            }
            #pragma unroll
            for (int ni = 0; ni < 4; ni++) {
                int p = ni >> 1, o = ni & 1;
                #pragma unroll
                for (int mi = 0; mi < 2; mi++) {
                    mma_f16(accG[mi][ni], a[mi], bg[p][o], bg[p][o + 2]);
                    mma_f16(accU[mi][ni], a[mi], bu[p][o], bu[p][o + 2]);
                }
            }
        }
        cons += STAGE_B; if (cons == (uint32_t)(NSTAGE * STAGE_B)) cons = 0;
    }

    // Epilogue: hid' = w * silu(gate) * up -> fp16
    #pragma unroll
    for (int mi = 0; mi < 2; mi++) {
        #pragma unroll
        for (int r2 = 0; r2 < 2; r2++) {
            int t = m0 + wm * 32 + mi * 16 + g + r2 * 8;
            float w = g_rw[t * TOPK + e];
            __half* dst = g_hid + (size_t)t * KC + (size_t)e * IDIM + n0;
            #pragma unroll
            for (int ni = 0; ni < 4; ni++) {
                int col = wn * 32 + ni * 8 + tg * 2;
                float gv0 = accG[mi][ni][r2 * 2 + 0], uv0 = accU[mi][ni][r2 * 2 + 0];
                float gv1 = accG[mi][ni][r2 * 2 + 1], uv1 = accU[mi][ni][r2 * 2 + 1];
                float h0 = (gv0 / (1.f + expf(-gv0))) * uv0 * w;
                float h1 = (gv1 / (1.f + expf(-gv1))) * uv1 * w;
                *(__half2*)(dst + col) = __floats2half2_rn(h0, h1);
            }
        }
    }
}

// ---------------------------------------------------------------------------
// GEMM2: out[4096,2048] = g_hid[4096,11264] @ down_flat[11264,2048]
// BM=128, BN=128, BK=64. B tile [k=64][n=128] (256B rows), ldmatrix.trans.
// 8 warps (4x2), warp 32x64. Strength-reduced mainloop addressing.
// ---------------------------------------------------------------------------
__global__ __launch_bounds__(256, 2) void gemm2_kernel(float* __restrict__ OUT)
{
    extern __shared__ __align__(128) char smem[];
    const uint32_t sbase = (uint32_t)__cvta_generic_to_shared(smem);
    const int m0 = blockIdx.x * 128;
    const int n0 = blockIdx.y * 128;

    const int tid = threadIdx.x;
    const int wid = tid >> 5, lane = tid & 31;
    const int wm = wid & 3, wn = wid >> 2;
    const int g = lane >> 2, tg = lane & 3;
    const int lr = lane & 7, hm = (lane >> 3) & 1, hk = lane >> 4;

    float acc[2][8][4] = {};
    const int KITER = KC / 64;   // 176

    auto load_stage = [&](uint32_t soff, int kk) {
        uint32_t st = sbase + soff;
        #pragma unroll
        for (int i = 0; i < 4; i++) {
            int idx = tid + i * 256;
            int row = idx >> 3, c = idx & 7;
            cp_async16(st + sw128(row, c), g_hid + (size_t)(m0 + row) * KC + kk + c * 8);
        }
        #pragma unroll
        for (int i = 0; i < 4; i++) {
            int idx = tid + i * 256;
            int r = idx >> 4, c = idx & 15;
            cp_async16(st + 16384 + sw256(r, c),
                       g_dwh + (size_t)(kk + r) * HDIM + n0 + c * 8);
        }
    };

    #pragma unroll
    for (int s = 0; s < NSTAGE - 1; s++) { load_stage((uint32_t)(s * STAGE_B), s * 64); cp_commit(); }

    uint32_t aB[2], bB[4];
    #pragma unroll
    for (int mi = 0; mi < 2; mi++)
        aB[mi] = ldsmA_base(sbase, wm * 32 + mi * 16, lr, hm, hk);
    #pragma unroll
    for (int p = 0; p < 4; p++)
        bB[p] = ldsmBt_base(sbase + 16384, 256, wn * 8 + p * 2, lr, hm, hk);

    uint32_t cons = 0, prod = (uint32_t)((NSTAGE - 1) * STAGE_B);
    for (int it = 0; it < KITER; it++) {
        cp_wait<NSTAGE - 2>();
        __syncthreads();

        int nxt = it + NSTAGE - 1;
        if (nxt < KITER) load_stage(prod, nxt * 64);
        cp_commit();
        prod += STAGE_B; if (prod == (uint32_t)(NSTAGE * STAGE_B)) prod = 0;

        #pragma unroll
        for (int ks = 0; ks < 4; ks++) {
            const uint32_t axor = (uint32_t)(ks << 5);
            const uint32_t brow = (uint32_t)(ks * 4096);   // 16 rows * 256B
            uint32_t a[2][4];
            #pragma unroll
            for (int mi = 0; mi < 2; mi++)
                ldsm4(a[mi], (aB[mi] + cons) ^ axor);
            uint32_t b[4][4];
            #pragma unroll
            for (int p = 0; p < 4; p++)
                ldsm4t(b[p], bB[p] + cons + brow);
            #pragma unroll
            for (int ni = 0; ni < 8; ni++) {
                int p = ni >> 1, o = ni & 1;
                #pragma unroll
                for (int mi = 0; mi < 2; mi++)
                    mma_f16(acc[mi][ni], a[mi], b[p][o], b[p][o + 2]);
            }
        }
        cons += STAGE_B; if (cons == (uint32_t)(NSTAGE * STAGE_B)) cons = 0;
    }

    #pragma unroll
    for (int mi = 0; mi < 2; mi++) {
        #pragma unroll
        for (int r2 = 0; r2 < 2; r2++) {
            int t = m0 + wm * 32 + mi * 16 + g + r2 * 8;
            #pragma unroll
            for (int ni = 0; ni < 8; ni++) {
                int col = n0 + wn * 64 + ni * 8 + tg * 2;
                float2 v;
                v.x = acc[mi][ni][r2 * 2 + 0];
                v.y = acc[mi][ni][r2 * 2 + 1];
                *(float2*)(OUT + (size_t)t * HDIM + col) = v;
            }
        }
    }
}

// ---------------------------------------------------------------------------
extern "C" void kernel_launch(void* const* d_in, const int* in_sizes, int n_in,
                              void* d_out, int out_size) {
    const float* x  = (const float*)d_in[0];
    const float* rw = (const float*)d_in[1];
    const float* gu = (const float*)d_in[2];
    const float* dw = (const float*)d_in[3];
    float* out = (float*)d_out;

    const long long OUT_ELEMS = (long long)T_TOK * HDIM;
    float* tail = nullptr;
    if ((long long)out_size >= OUT_ELEMS + (long long)T_TOK * TOPK)
        tail = out + OUT_ELEMS;

    cudaFuncSetAttribute(gemm1_kernel, cudaFuncAttributeMaxDynamicSharedMemorySize, G_SMEM);
    cudaFuncSetAttribute(gemm2_kernel, cudaFuncAttributeMaxDynamicSharedMemorySize, G_SMEM);

    tpose_rw_kernel<<<(NEXP * HDIM + 255) / 256, 256>>>(rw);
    router_kernel<<<T_TOK / 8, 256>>>(x, tail);
    cvt_all_kernel<<<9472, 256>>>(gu, dw, x);

    dim3 grid1(T_TOK / 128, IDIM / 64, TOPK);   // (32, 22, 8)
    gemm1_kernel<<<grid1, 256, G_SMEM>>>();

    dim3 grid2(T_TOK / 128, HDIM / 128);        // (32, 16)
    gemm2_kernel<<<grid2, 256, G_SMEM>>>(out);
}